// round 1
// baseline (speedup 1.0000x reference)
#include <cuda_runtime.h>
#include <cuda_bf16.h>
#include <cstdint>

// ---------------- problem constants ----------------
#define BATCH 64
#define DIN   176
#define HID   512
#define G4    2048          // 4*HID
#define T_ENC 1025          // 1 + 1024
#define T_DEC 1023          // TTGT - 1
#define MROWS_MAX (BATCH * T_ENC)   // 65600

// ---------------- scratch (static device globals; no cudaMalloc allowed) ----
__device__ float g_gx  [(size_t)MROWS_MAX * G4];   // 537 MB: per-layer gx, also reused as hmid
__device__ float g_seqA[(size_t)MROWS_MAX * HID];  // hidden sequence buffer
__device__ float g_seqB[(size_t)MROWS_MAX * HID];  // dec_out
__device__ float g_xpad[(size_t)MROWS_MAX * DIN];  // padded inputs
__device__ float g_hpub[2 * BATCH * HID];          // ping-pong published h
__device__ float g_hT0[BATCH * HID], g_cT0[BATCH * HID];
__device__ float g_hT1[BATCH * HID], g_cT1[BATCH * HID];
__device__ float g_hTd[BATCH * HID], g_cTd[BATCH * HID];
__device__ unsigned g_bar[4];

// ---------------- small utility kernels ----------------
__global__ void reset_bar_kernel(unsigned* bar) {
    if (threadIdx.x < 4) bar[threadIdx.x] = 0u;
}

// dst[b][t][:] = (t==0 || t>Tcopy) ? 0 : src[b][t-1][:]
__global__ void pad_shift_kernel(const float* __restrict__ src, float* __restrict__ dst,
                                 int Tsrc, int Tpad, int Tcopy) {
    long n = (long)BATCH * Tpad * DIN;
    long i = (long)blockIdx.x * blockDim.x + threadIdx.x;
    if (i >= n) return;
    int d = (int)(i % DIN);
    long bt = i / DIN;
    int t = (int)(bt % Tpad);
    int b = (int)(bt / Tpad);
    dst[i] = (t == 0 || t > Tcopy) ? 0.f : src[((long)b * Tsrc + (t - 1)) * DIN + d];
}

__global__ void zero_t0_kernel(float* __restrict__ out) {
    int i = blockIdx.x * blockDim.x + threadIdx.x;
    if (i < BATCH * DIN) {
        int b = i / DIN, d = i % DIN;
        out[(size_t)b * 1024 * DIN + d] = 0.f;
    }
}

// ---------------- generic fp32 GEMM: C = A(MxK) * W(NxK)^T + b1 + b2 --------
// 128x128 CTA tile, 256 threads, 8x8 per-thread micro tile, K%8==0 required.
// remapT>0: row m -> (b=m/remapT, t=m%remapT) stored at row b*(remapT+1)+t+1 (ld=N).
__global__ void __launch_bounds__(256, 2)
gemm_bias_kernel(const float* __restrict__ A, const float* __restrict__ W,
                 const float* __restrict__ b1, const float* __restrict__ b2,
                 float* __restrict__ C, int M, int N, int K,
                 int relu, int remapT) {
    __shared__ float As[8][132];
    __shared__ float Bs[8][132];
    const int row0 = blockIdx.y * 128;
    const int col0 = blockIdx.x * 128;
    const int tid = threadIdx.x;
    const int lm = tid >> 1;
    const int lk = (tid & 1) * 4;
    const int tx = tid & 15;
    const int ty = tid >> 4;

    float acc[8][8];
#pragma unroll
    for (int i = 0; i < 8; i++)
#pragma unroll
        for (int j = 0; j < 8; j++) acc[i][j] = 0.f;

    for (int kc = 0; kc < K; kc += 8) {
        float4 av = make_float4(0.f, 0.f, 0.f, 0.f);
        int ar = row0 + lm;
        if (ar < M) av = *(const float4*)&A[(size_t)ar * K + kc + lk];
        As[lk + 0][lm] = av.x; As[lk + 1][lm] = av.y;
        As[lk + 2][lm] = av.z; As[lk + 3][lm] = av.w;

        float4 bv = make_float4(0.f, 0.f, 0.f, 0.f);
        int wr = col0 + lm;
        if (wr < N) bv = *(const float4*)&W[(size_t)wr * K + kc + lk];
        Bs[lk + 0][lm] = bv.x; Bs[lk + 1][lm] = bv.y;
        Bs[lk + 2][lm] = bv.z; Bs[lk + 3][lm] = bv.w;
        __syncthreads();

#pragma unroll
        for (int k = 0; k < 8; k++) {
            float a[8], b[8];
            *(float4*)&a[0] = *(float4*)&As[k][ty * 8];
            *(float4*)&a[4] = *(float4*)&As[k][ty * 8 + 4];
            *(float4*)&b[0] = *(float4*)&Bs[k][tx * 8];
            *(float4*)&b[4] = *(float4*)&Bs[k][tx * 8 + 4];
#pragma unroll
            for (int i = 0; i < 8; i++)
#pragma unroll
                for (int j = 0; j < 8; j++) acc[i][j] += a[i] * b[j];
        }
        __syncthreads();
    }

#pragma unroll
    for (int j = 0; j < 8; j++) {
        int cidx = col0 + tx * 8 + j;
        if (cidx >= N) continue;
        float bias = (b1 ? b1[cidx] : 0.f) + (b2 ? b2[cidx] : 0.f);
#pragma unroll
        for (int i = 0; i < 8; i++) {
            int r = row0 + ty * 8 + i;
            if (r >= M) continue;
            size_t rowbase;
            if (remapT > 0) {
                int bb = r / remapT;
                int tt = r - bb * remapT;
                rowbase = ((size_t)bb * (remapT + 1) + tt + 1) * (size_t)N;
            } else {
                rowbase = (size_t)r * N;
            }
            float v = acc[i][j] + bias;
            if (relu) v = fmaxf(v, 0.f);
            C[rowbase + cidx] = v;
        }
    }
}

// ---------------- persistent LSTM scan ----------------
// Grid: 128 CTAs = 4 batch-groups(16 batches) x 32 hidden-tiles(16 hidden).
// Whh slice (64 gate-rows x 512) lives in smem for the whole scan.
// c state in registers. h published through ping-pong global buffer + sw barrier.
#define SCAN_SMEM_FLOATS (512 * 68 + 512 * 20 + 8192)
#define SCAN_SMEM_BYTES  (SCAN_SMEM_FLOATS * 4)

__device__ __forceinline__ float sigf(float x) { return 1.f / (1.f + expf(-x)); }

__device__ __forceinline__ void group_barrier(unsigned* bar, int bg, unsigned target) {
    __threadfence();          // release: make this thread's global writes visible
    __syncthreads();          // all threads of CTA have fenced
    if (threadIdx.x == 0) {
        atomicAdd(&bar[bg], 1u);
        while (atomicAdd(&bar[bg], 0u) < target) { }
        __threadfence();      // acquire side
    }
    __syncthreads();
}

__global__ void __launch_bounds__(256, 1)
lstm_scan_kernel(const float* __restrict__ gx, const float* __restrict__ Whh,
                 const float* __restrict__ h0, const float* __restrict__ c0,
                 float* __restrict__ hs_out, float* __restrict__ hT_out,
                 float* __restrict__ cT_out, float* __restrict__ hpub,
                 unsigned* __restrict__ bar, int T) {
    extern __shared__ float sm[];
    float* w_s = sm;                    // [512][68]  transposed weights w_s[k*68+gr]
    float* h_s = w_s + 512 * 68;        // [512][20]  transposed h_prev  h_s[k*20+b]
    float* red = h_s + 512 * 20;        // [8][16][64] partials red[s*1024+b*64+gr]

    const int tid = threadIdx.x;
    const int bg = blockIdx.x >> 5;     // batch group 0..3
    const int ht = blockIdx.x & 31;     // hidden tile 0..31
    const int B0 = bg * 16;
    const int J0 = ht * 16;

    // ---- load Whh slice into smem (once) ----
    {
        int gr = tid >> 2;              // 0..63  (g = gr>>4, j = gr&15)
        int g = gr >> 4, j = gr & 15;
        int k0 = (tid & 3) * 128;
        const float* wrow = Whh + ((size_t)(g * 512 + J0 + j)) * 512 + k0;
#pragma unroll 4
        for (int k = 0; k < 128; k++) w_s[(k0 + k) * 68 + gr] = wrow[k];
    }

    // ---- init states ----
    const int ub = tid >> 4;            // batch within tile (0..15)
    const int uj = tid & 15;            // hidden within tile (0..15)
    float cval = c0 ? c0[(B0 + ub) * 512 + J0 + uj] : 0.f;
    float hval = h0 ? h0[(B0 + ub) * 512 + J0 + uj] : 0.f;
    hpub[32768 + (B0 + ub) * 512 + J0 + uj] = hval;   // parity-1 slot feeds t=0

    unsigned nbar = 1;
    group_barrier(bar, bg, nbar * 32);

    // compute-phase thread mapping
    const int s   = tid >> 5;           // k-slice 0..7 (64 k each)
    const int o   = tid & 31;
    const int ob2 = (o >> 3) << 2;      // batch sub-offset 0,4,8,12
    const int og8 = (o & 7) << 3;       // gate-row sub-offset 0..56

    for (int t = 0; t < T; ++t) {
        const float* hsrc = hpub + (((t + 1) & 1) << 15);   // *32768

        // phase 1: load h_prev (L2-coherent, bypass L1)
#pragma unroll
        for (int i = 0; i < 32; ++i) {
            int b = i >> 1;
            int k = tid + ((i & 1) << 8);
            h_s[k * 20 + b] = __ldcg(hsrc + (B0 + b) * 512 + k);
        }
        __syncthreads();

        // phase 2: partial dot products, 4 batches x 8 gate-rows over 64 k
        float acc[4][8];
#pragma unroll
        for (int bb = 0; bb < 4; bb++)
#pragma unroll
            for (int rr = 0; rr < 8; rr++) acc[bb][rr] = 0.f;

        const float* hptr = &h_s[(s * 64) * 20 + ob2];
        const float* wptr = &w_s[(s * 64) * 68 + og8];
#pragma unroll 4
        for (int kk = 0; kk < 64; ++kk) {
            float4 h4 = *(const float4*)hptr;  hptr += 20;
            float4 w0 = *(const float4*)wptr;
            float4 w1 = *(const float4*)(wptr + 4); wptr += 68;
#define FMA8(BB, HV)                                                    \
            acc[BB][0] += (HV) * w0.x; acc[BB][1] += (HV) * w0.y;       \
            acc[BB][2] += (HV) * w0.z; acc[BB][3] += (HV) * w0.w;       \
            acc[BB][4] += (HV) * w1.x; acc[BB][5] += (HV) * w1.y;       \
            acc[BB][6] += (HV) * w1.z; acc[BB][7] += (HV) * w1.w;
            FMA8(0, h4.x) FMA8(1, h4.y) FMA8(2, h4.z) FMA8(3, h4.w)
#undef FMA8
        }

        // phase 3: write partials
#pragma unroll
        for (int bb = 0; bb < 4; bb++) {
            float4 v0 = make_float4(acc[bb][0], acc[bb][1], acc[bb][2], acc[bb][3]);
            float4 v1 = make_float4(acc[bb][4], acc[bb][5], acc[bb][6], acc[bb][7]);
            int base = s * 1024 + (ob2 + bb) * 64 + og8;
            *(float4*)&red[base]     = v0;
            *(float4*)&red[base + 4] = v1;
        }
        __syncthreads();

        // phase 4: reduce k-slices, add gx, elementwise LSTM cell (thread = (b,j))
        float gi = 0.f, gf = 0.f, gg = 0.f, go = 0.f;
#pragma unroll
        for (int s2 = 0; s2 < 8; s2++) {
            const float* rp = &red[s2 * 1024 + ub * 64 + uj];
            gi += rp[0]; gf += rp[16]; gg += rp[32]; go += rp[48];
        }
        const float* gxp = gx + ((size_t)(B0 + ub) * T + t) * G4 + J0 + uj;
        gi += gxp[0]; gf += gxp[512]; gg += gxp[1024]; go += gxp[1536];

        float ig = sigf(gi), fg = sigf(gf), og_ = sigf(go), gt = tanhf(gg);
        cval = fg * cval + ig * gt;
        hval = og_ * tanhf(cval);

        hpub[((t & 1) << 15) + (B0 + ub) * 512 + J0 + uj] = hval;
        if (hs_out)
            hs_out[((size_t)(B0 + ub) * T + t) * 512 + J0 + uj] = hval;

        ++nbar;
        group_barrier(bar, bg, nbar * 32);
    }

    hT_out[(B0 + ub) * 512 + J0 + uj] = hval;
    cT_out[(B0 + ub) * 512 + J0 + uj] = cval;
}

// ---------------- host orchestration ----------------
static void launch_gemm(const float* A, const float* W, const float* b1, const float* b2,
                        float* C, int M, int N, int K, int relu, int remapT) {
    dim3 grid((N + 127) / 128, (M + 127) / 128);
    gemm_bias_kernel<<<grid, 256>>>(A, W, b1, b2, C, M, N, K, relu, remapT);
}

extern "C" void kernel_launch(void* const* d_in, const int* in_sizes, int n_in,
                              void* d_out, int out_size) {
    (void)in_sizes; (void)n_in; (void)out_size;
    const float* x        = (const float*)d_in[0];
    const float* y        = (const float*)d_in[1];
    const float* eWih0    = (const float*)d_in[2];
    const float* eWhh0    = (const float*)d_in[3];
    const float* ebih0    = (const float*)d_in[4];
    const float* ebhh0    = (const float*)d_in[5];
    const float* eWih1    = (const float*)d_in[6];
    const float* eWhh1    = (const float*)d_in[7];
    const float* ebih1    = (const float*)d_in[8];
    const float* ebhh1    = (const float*)d_in[9];
    const float* dWih0    = (const float*)d_in[10];
    const float* dWhh0    = (const float*)d_in[11];
    const float* dbih0    = (const float*)d_in[12];
    const float* dbhh0    = (const float*)d_in[13];
    const float* dWih1    = (const float*)d_in[14];
    const float* dWhh1    = (const float*)d_in[15];
    const float* dbih1    = (const float*)d_in[16];
    const float* dbhh1    = (const float*)d_in[17];
    const float* clsW1    = (const float*)d_in[18];
    const float* clsb1    = (const float*)d_in[19];
    const float* clsW2    = (const float*)d_in[20];
    const float* clsb2    = (const float*)d_in[21];
    float* out = (float*)d_out;

    float *gx, *seqA, *seqB, *xpad, *hpub, *hT0, *cT0, *hT1, *cT1, *hTd, *cTd;
    unsigned* bar;
    cudaGetSymbolAddress((void**)&gx,   g_gx);
    cudaGetSymbolAddress((void**)&seqA, g_seqA);
    cudaGetSymbolAddress((void**)&seqB, g_seqB);
    cudaGetSymbolAddress((void**)&xpad, g_xpad);
    cudaGetSymbolAddress((void**)&hpub, g_hpub);
    cudaGetSymbolAddress((void**)&hT0,  g_hT0);
    cudaGetSymbolAddress((void**)&cT0,  g_cT0);
    cudaGetSymbolAddress((void**)&hT1,  g_hT1);
    cudaGetSymbolAddress((void**)&cT1,  g_cT1);
    cudaGetSymbolAddress((void**)&hTd,  g_hTd);
    cudaGetSymbolAddress((void**)&cTd,  g_cTd);
    cudaGetSymbolAddress((void**)&bar,  g_bar);

    cudaFuncSetAttribute(lstm_scan_kernel,
                         cudaFuncAttributeMaxDynamicSharedMemorySize, SCAN_SMEM_BYTES);

    const int ME = BATCH * T_ENC;   // 65600
    const int MD = BATCH * T_DEC;   // 65472

    // ---------------- encoder ----------------
    {
        long n = (long)BATCH * T_ENC * DIN;
        pad_shift_kernel<<<(int)((n + 255) / 256), 256>>>(x, xpad, 1024, T_ENC, 1024);
    }
    launch_gemm(xpad, eWih0, ebih0, ebhh0, gx, ME, G4, DIN, 0, 0);
    reset_bar_kernel<<<1, 32>>>(bar);
    lstm_scan_kernel<<<128, 256, SCAN_SMEM_BYTES>>>(gx, eWhh0, nullptr, nullptr,
                                                    seqA, hT0, cT0, hpub, bar, T_ENC);
    launch_gemm(seqA, eWih1, ebih1, ebhh1, gx, ME, G4, HID, 0, 0);
    reset_bar_kernel<<<1, 32>>>(bar);
    lstm_scan_kernel<<<128, 256, SCAN_SMEM_BYTES>>>(gx, eWhh1, nullptr, nullptr,
                                                    nullptr, hT1, cT1, hpub, bar, T_ENC);

    // ---------------- decoder ----------------
    {
        long n = (long)BATCH * T_DEC * DIN;
        pad_shift_kernel<<<(int)((n + 255) / 256), 256>>>(y, xpad, 1024, T_DEC, 1022);
    }
    launch_gemm(xpad, dWih0, dbih0, dbhh0, gx, MD, G4, DIN, 0, 0);
    reset_bar_kernel<<<1, 32>>>(bar);
    lstm_scan_kernel<<<128, 256, SCAN_SMEM_BYTES>>>(gx, dWhh0, hT0, cT0,
                                                    seqA, hTd, cTd, hpub, bar, T_DEC);
    launch_gemm(seqA, dWih1, dbih1, dbhh1, gx, MD, G4, HID, 0, 0);
    reset_bar_kernel<<<1, 32>>>(bar);
    lstm_scan_kernel<<<128, 256, SCAN_SMEM_BYTES>>>(gx, dWhh1, hT1, cT1,
                                                    seqB, hTd, cTd, hpub, bar, T_DEC);

    // ---------------- classifier ----------------
    // hmid = relu(dec_out @ W1^T + b1)  -> stored in gx buffer (ld = 256)
    launch_gemm(seqB, clsW1, clsb1, nullptr, gx, MD, 256, HID, 1, 0);
    // logits -> out[b][t+1][:], row remap, ld = DIN
    launch_gemm(gx, clsW2, clsb2, nullptr, out, MD, DIN, 256, 0, T_DEC);
    zero_t0_kernel<<<(BATCH * DIN + 255) / 256, 256>>>(out);
}